// round 10
// baseline (speedup 1.0000x reference)
#include <cuda_runtime.h>
#include <cuda_fp16.h>
#include <cstdint>

#define NB 8
#define NPIX 4096
#define CCH 64

// ---------------- scratch (no allocation allowed) ----------------
__device__ __align__(16) __half g_QhT[NB * CCH * NPIX];  // [b][c][n]
__device__ __align__(16) __half g_QlT[NB * CCH * NPIX];
__device__ __align__(16) __half g_KhT[NB * CCH * NPIX];
__device__ __align__(16) __half g_Qh[NB * NPIX * CCH];   // [b][m][c]
__device__ __align__(16) __half g_Ql[NB * NPIX * CCH];
__device__ __align__(16) __half g_Kh[NB * NPIX * CCH];
__device__ __align__(16) __half g_Vh[NB * CCH * NPIX];   // [b][c][n]
__device__ float g_G[NB * CCH * NPIX];    // sigmoid gate [b][c][m]
__device__ float g_GS[NB * NPIX];         // gate strength [b][m]
// packed weights: rows 0-63 Wq, 64-127 Wk, 128-191 Wv, 192-255 Wg, 256-511 W1
__device__ __align__(16) __half g_Wh[512 * 64];
__device__ __align__(16) __half g_Wl[512 * 64];
__device__ float g_bias[512];

// ---------------- weight prep kernel ----------------
__global__ __launch_bounds__(256) void prep_kernel(
    const float* __restrict__ Wq, const float* __restrict__ bq,
    const float* __restrict__ Wk, const float* __restrict__ bk,
    const float* __restrict__ Wv, const float* __restrict__ bv,
    const float* __restrict__ Wg, const float* __restrict__ bg,
    const float* __restrict__ W1, const float* __restrict__ b1) {
    int idx = blockIdx.x * 256 + threadIdx.x;   // 0..32767
    int row = idx >> 6, c = idx & 63;
    float w;
    if (row < 64)       w = Wq[row * 64 + c];
    else if (row < 128) w = Wk[(row - 64) * 64 + c];
    else if (row < 192) w = Wv[(row - 128) * 64 + c];
    else if (row < 256) w = Wg[(row - 192) * 64 + c];
    else                w = W1[(row - 256) * 64 + c];
    __half h = __float2half(w);
    g_Wh[idx] = h;
    g_Wl[idx] = __float2half(w - __half2float(h));
    if (c == 0) {
        float bv_;
        if (row < 64)       bv_ = bq[row];
        else if (row < 128) bv_ = bk[row - 64];
        else if (row < 192) bv_ = bv[row - 128];
        else if (row < 256) bv_ = bg[row - 192];
        else                bv_ = b1[row - 256];
        g_bias[row] = bv_;
    }
}

// ---------------- mma helpers ----------------
__device__ __forceinline__ void mma_f16(float* d, uint32_t a0, uint32_t a1,
                                        uint32_t a2, uint32_t a3,
                                        uint32_t b0, uint32_t b1) {
    asm volatile(
        "mma.sync.aligned.m16n8k16.row.col.f32.f16.f16.f32 "
        "{%0,%1,%2,%3}, {%4,%5,%6,%7}, {%8,%9}, {%0,%1,%2,%3};"
        : "+f"(d[0]), "+f"(d[1]), "+f"(d[2]), "+f"(d[3])
        : "r"(a0), "r"(a1), "r"(a2), "r"(a3), "r"(b0), "r"(b1));
}

__device__ __forceinline__ void ldmx4(uint32_t& r0, uint32_t& r1, uint32_t& r2,
                                      uint32_t& r3, uint32_t a) {
    asm volatile("ldmatrix.sync.aligned.m8n8.x4.shared.b16 {%0,%1,%2,%3}, [%4];"
                 : "=r"(r0), "=r"(r1), "=r"(r2), "=r"(r3) : "r"(a));
}

__device__ __forceinline__ void ldmx4t(uint32_t& r0, uint32_t& r1, uint32_t& r2,
                                       uint32_t& r3, uint32_t a) {
    asm volatile("ldmatrix.sync.aligned.m8n8.x4.trans.shared.b16 {%0,%1,%2,%3}, [%4];"
                 : "=r"(r0), "=r"(r1), "=r"(r2), "=r"(r3) : "r"(a));
}

__device__ __forceinline__ uint32_t pack_h2(float a, float b) {
    __half2 h = __floats2half2_rn(a, b);
    return *(uint32_t*)&h;
}

__device__ __forceinline__ void cp16(uint32_t s, const void* g) {
    asm volatile("cp.async.cg.shared.global [%0], [%1], 16;"
                 :: "r"(s), "l"(g) : "memory");
}

// ---------------- tensor-core projection kernel (unchanged) ----------------
#define SW_H 0
#define SW_L 73728
#define SX_H 147456
#define SX_L 164864
#define SBIAS 182272
#define SW2B 184320
#define SMVAL 185344
#define SGSP 185856
#define PROJ_SMEM 187904

__global__ __launch_bounds__(256, 1) void proj_mma(
    const float* __restrict__ x, const float* __restrict__ mask,
    const unsigned int* __restrict__ flags,
    const float* __restrict__ W2, const float* __restrict__ b2) {
    const int b = blockIdx.y;
    if (flags[b] == 0u) return;
    const int n0 = blockIdx.x * 128;

    extern __shared__ __align__(16) char sm[];
    uint32_t sb;
    asm("{ .reg .u64 t; cvta.to.shared.u64 t, %1; cvt.u32.u64 %0, t; }"
        : "=r"(sb) : "l"(sm));

    const int tid = threadIdx.x;
    const int wid = tid >> 5, lane = tid & 31;
    const int g = lane >> 2, t = lane & 3, q8 = lane & 7;

    for (int i = tid; i < 4096; i += 256) {
        int row = i >> 3, c8 = i & 7;
        *(uint4*)(sm + SW_H + row * 144 + c8 * 16) = ((const uint4*)g_Wh)[i];
        *(uint4*)(sm + SW_L + row * 144 + c8 * 16) = ((const uint4*)g_Wl)[i];
    }
    for (int i = tid; i < 2048; i += 256) {
        int c = i >> 5, n4 = i & 31;
        float4 xv = *(const float4*)(x + (size_t)b * (CCH * NPIX) +
                                     (size_t)c * NPIX + n0 + n4 * 4);
        __half h0 = __float2half(xv.x), h1 = __float2half(xv.y);
        __half h2 = __float2half(xv.z), h3 = __float2half(xv.w);
        uint2 hi, lo;
        {
            __half2 p0 = __halves2half2(h0, h1), p1 = __halves2half2(h2, h3);
            hi.x = *(uint32_t*)&p0; hi.y = *(uint32_t*)&p1;
        }
        lo.x = pack_h2(xv.x - __half2float(h0), xv.y - __half2float(h1));
        lo.y = pack_h2(xv.z - __half2float(h2), xv.w - __half2float(h3));
        *(uint2*)(sm + SX_H + c * 272 + n4 * 8) = hi;
        *(uint2*)(sm + SX_L + c * 272 + n4 * 8) = lo;
    }
    float* sBias = (float*)(sm + SBIAS);
    float* sW2 = (float*)(sm + SW2B);
    float* sMval = (float*)(sm + SMVAL);
    float* sGSp = (float*)(sm + SGSP);
    for (int i = tid; i < 512; i += 256) sBias[i] = g_bias[i];
    for (int i = tid; i < 256; i += 256) sW2[i] = W2[i];
    if (tid < 128) sMval[tid] = mask[b * NPIX + n0 + tid];
    __syncthreads();

    const uint32_t thrA = (uint32_t)(q8 + ((lane >> 3) & 1) * 8) * 144 +
                          ((lane >> 4) & 1) * 16;
    const uint32_t thrB = (uint32_t)(q8 + ((lane >> 3) & 1) * 8) * 272 +
                          ((lane >> 4) & 1) * 16;
    const float b2v = __ldg(b2);

    for (int nhalf = 0; nhalf < 2; nhalf++) {
        const int nb0 = nhalf * 64;
        for (int mpass = 0; mpass < 2; mpass++) {
            float d[2][8][4];
#pragma unroll
            for (int mt = 0; mt < 2; mt++)
#pragma unroll
                for (int nt = 0; nt < 8; nt++)
#pragma unroll
                    for (int q = 0; q < 4; q++) d[mt][nt][q] = 0.f;

            const uint32_t mrowbase = (uint32_t)(mpass * 256 + wid * 32) * 144;
#pragma unroll
            for (int pass = 0; pass < 3; pass++) {
                const uint32_t abase = sb + (pass < 2 ? SW_H : SW_L) + thrA + mrowbase;
                const uint32_t bbase = sb + (pass == 1 ? SX_L : SX_H) + thrB + nb0 * 2;
#pragma unroll
                for (int k = 0; k < 4; k++) {
                    uint32_t bf[4][4];
#pragma unroll
                    for (int ng = 0; ng < 4; ng++)
                        ldmx4t(bf[ng][0], bf[ng][1], bf[ng][2], bf[ng][3],
                               bbase + (uint32_t)k * (16 * 272) + ng * 32);
                    uint32_t af[2][4];
#pragma unroll
                    for (int mt = 0; mt < 2; mt++)
                        ldmx4(af[mt][0], af[mt][1], af[mt][2], af[mt][3],
                              abase + (uint32_t)mt * (16 * 144) + k * 32);
#pragma unroll
                    for (int mt = 0; mt < 2; mt++)
#pragma unroll
                        for (int ng = 0; ng < 4; ng++) {
                            mma_f16(d[mt][2 * ng], af[mt][0], af[mt][1], af[mt][2],
                                    af[mt][3], bf[ng][0], bf[ng][1]);
                            mma_f16(d[mt][2 * ng + 1], af[mt][0], af[mt][1], af[mt][2],
                                    af[mt][3], bf[ng][2], bf[ng][3]);
                        }
                }
            }

            if (mpass == 0) {
                const int sec = wid >> 1;
#pragma unroll
                for (int mt = 0; mt < 2; mt++) {
#pragma unroll
                    for (int ri = 0; ri < 2; ri++) {
                        const int ogl = wid * 32 + mt * 16 + g + ri * 8;
                        const int o = (wid & 1) * 32 + mt * 16 + g + ri * 8;
                        const float bias = sBias[ogl];
                        const size_t rowoff = (size_t)(b * 64 + o) * NPIX + n0;
#pragma unroll
                        for (int nt = 0; nt < 8; nt++) {
                            const int nl = nb0 + nt * 8 + 2 * t;
                            const float a0 = d[mt][nt][ri * 2 + 0];
                            const float a1 = d[mt][nt][ri * 2 + 1];
                            if (sec == 0 || sec == 1) {
                                const float m0 = sMval[nl], m1 = sMval[nl + 1];
                                const float v0 = bias + m0 * a0;
                                const float v1 = bias + m1 * a1;
                                __half h0 = __float2half(v0), h1 = __float2half(v1);
                                uint32_t hi = *(uint32_t*)&h0 |
                                              ((uint32_t)*(uint16_t*)&h1 << 16);
                                uint32_t lo = pack_h2(v0 - __half2float(h0),
                                                      v1 - __half2float(h1));
                                if (sec == 0) {
                                    *(uint32_t*)(g_QhT + rowoff + nl) = hi;
                                    *(uint32_t*)(g_QlT + rowoff + nl) = lo;
                                } else {
                                    *(uint32_t*)(g_KhT + rowoff + nl) = hi;
                                }
                            } else if (sec == 2) {
                                const float v0 = bias + a0, v1 = bias + a1;
                                *(uint32_t*)(g_Vh + rowoff + nl) = pack_h2(v0, v1);
                            } else {
                                const float v0 = bias + a0, v1 = bias + a1;
                                float2 gg;
                                gg.x = 1.f / (1.f + __expf(-v0));
                                gg.y = 1.f / (1.f + __expf(-v1));
                                *(float2*)(g_G + rowoff + nl) = gg;
                            }
                        }
                    }
                }
            } else {
                float gsp[16];
#pragma unroll
                for (int i = 0; i < 16; i++) gsp[i] = 0.f;
#pragma unroll
                for (int mt = 0; mt < 2; mt++) {
#pragma unroll
                    for (int ri = 0; ri < 2; ri++) {
                        const int o = wid * 32 + mt * 16 + g + ri * 8;
                        const float bias = sBias[256 + o];
                        const float w2v = sW2[o];
#pragma unroll
                        for (int nt = 0; nt < 8; nt++) {
                            float h0 = bias + d[mt][nt][ri * 2 + 0];
                            float h1 = bias + d[mt][nt][ri * 2 + 1];
                            gsp[nt * 2 + 0] += w2v * fmaxf(h0, 0.f);
                            gsp[nt * 2 + 1] += w2v * fmaxf(h1, 0.f);
                        }
                    }
                }
#pragma unroll
                for (int off = 4; off < 32; off <<= 1)
#pragma unroll
                    for (int i = 0; i < 16; i++)
                        gsp[i] += __shfl_xor_sync(0xffffffffu, gsp[i], off);
                if (lane < 4) {
#pragma unroll
                    for (int nt = 0; nt < 8; nt++) {
                        sGSp[wid * 64 + nt * 8 + 2 * lane + 0] = gsp[nt * 2 + 0];
                        sGSp[wid * 64 + nt * 8 + 2 * lane + 1] = gsp[nt * 2 + 1];
                    }
                }
                __syncthreads();
                if (tid < 64) {
                    float s = b2v;
#pragma unroll
                    for (int w = 0; w < 8; w++) s += sGSp[w * 64 + tid];
                    g_GS[b * NPIX + n0 + nb0 + tid] = 1.f / (1.f + __expf(-s));
                }
                __syncthreads();
            }
        }
    }
}

// ---------------- transpose kernel: [b][c][n] -> [b][n][c] -------------
__global__ __launch_bounds__(256) void transpose_qk(const unsigned int* __restrict__ flags) {
    const int b = blockIdx.z;
    if (flags[b] == 0u) return;
    const int arr = blockIdx.y;
    const int n0 = blockIdx.x * 64;
    const __half* src = arr == 0 ? g_QhT : (arr == 1 ? g_QlT : g_KhT);
    __half* dst = arr == 0 ? g_Qh : (arr == 1 ? g_Ql : g_Kh);
    const uint32_t* in = (const uint32_t*)(src + (size_t)b * CCH * NPIX);
    uint32_t* out = (uint32_t*)(dst + (size_t)b * NPIX * CCH);

    __shared__ uint32_t s[64 * 33];
    const int tid = threadIdx.x;
#pragma unroll
    for (int i = 0; i < 8; i++) {
        int idx = i * 256 + tid;
        int c = idx >> 5, n2 = idx & 31;
        s[c * 33 + n2] = in[(size_t)c * (NPIX / 2) + (n0 >> 1) + n2];
    }
    __syncthreads();
#pragma unroll
    for (int i = 0; i < 8; i++) {
        int idx = i * 256 + tid;
        int n = idx >> 5, c2 = idx & 31;
        uint32_t u0 = s[(2 * c2) * 33 + (n >> 1)];
        uint32_t u1 = s[(2 * c2 + 1) * 33 + (n >> 1)];
        uint32_t sel = (n & 1) ? 0x7632u : 0x5410u;
        out[(size_t)(n0 + n) * 32 + c2] = __byte_perm(u0, u1, sel);
    }
}

// ---------------- fp16 flash attention: BM=64, warp pairs split keys -------
#define KH_OFF 0
#define VH_OFF 18432
#define BUFSZ 35840
#define QSTG BUFSZ                 // Q staging in buf1 (transient)
#define SMEM_ATTN (2 * BUFSZ)
#define SOFTMAX_SHIFT 8.0f

__global__ __launch_bounds__(256, 2) void attn_kernel(
    const float* __restrict__ x, const unsigned int* __restrict__ flags,
    float* __restrict__ out) {
    const int b = blockIdx.y;
    const int m0 = blockIdx.x * 64;
    const int tid = threadIdx.x;

    if (flags[b] == 0u) {
        const float* xb = x + (size_t)b * (CCH * NPIX) + m0;
        float* ob = out + (size_t)b * (CCH * NPIX) + m0;
        for (int i = tid; i < 4096; i += 256) {
            int d = i >> 6, m = i & 63;
            ob[(size_t)d * NPIX + m] = xb[(size_t)d * NPIX + m];
        }
        return;
    }

    extern __shared__ __align__(16) char smem[];
    uint32_t sbase;
    asm("{ .reg .u64 t; cvta.to.shared.u64 t, %1; cvt.u32.u64 %0, t; }"
        : "=r"(sbase) : "l"(smem));

    const int wid = tid >> 5, lane = tid & 31;
    const int g = lane >> 2, t = lane & 3;
    const int rg = wid & 3;          // row group: rows rg*16 .. rg*16+15
    const int kh = wid >> 2;         // key half: keys kh*64 .. kh*64+63
    const int rowA = rg * 16 + g;    // m-row within the 64-row tile

    const int q8 = lane & 7;
    // A-fragment selectors (row.col mma, ldmatrix.x4): rows by bit3, cols by bit4
    const uint32_t rselA = q8 + ((lane >> 3) & 1) * 8;
    const uint32_t cselA = ((lane >> 4) & 1) * 16;
    // B-fragment selectors: rows by bit4, cols by bit3  (round-8 validated)
    const uint32_t rselB = q8 + ((lane >> 4) & 1) * 8;
    const uint32_t cselB = ((lane >> 3) & 1) * 16;

    const uint4* khg = (const uint4*)(g_Kh + (size_t)b * NPIX * 64);
    const uint4* vhg = (const uint4*)(g_Vh + (size_t)b * 64 * NPIX);

    // ---- stage Q tile (64 x 64, hi/lo) into buf1 (transient) ----
    {
        const uint4* qh = (const uint4*)(g_Qh + ((size_t)b * NPIX + m0) * 64);
        const uint4* ql = (const uint4*)(g_Ql + ((size_t)b * NPIX + m0) * 64);
#pragma unroll
        for (int i = 0; i < 2; i++) {
            int idx = tid + i * 256;   // 0..511
            int r = idx >> 3, c = idx & 7;
            *(uint4*)(smem + QSTG + r * 144 + c * 16) = qh[idx];
            *(uint4*)(smem + QSTG + 9216 + r * 144 + c * 16) = ql[idx];
        }
    }

    // ---- prologue: cp.async tile 0 into buf0 ----
#pragma unroll
    for (int i = 0; i < 4; i++) {
        int idx = tid + i * 256;
        int rk = idx >> 3, ck = idx & 7;
        cp16(sbase + KH_OFF + rk * 144 + ck * 16, &khg[(size_t)rk * 8 + ck]);
        int rv = idx >> 4, cv = idx & 15;
        cp16(sbase + VH_OFF + rv * 272 + cv * 16, &vhg[(size_t)rv * 512 + cv]);
    }
    asm volatile("cp.async.commit_group;" ::: "memory");
    asm volatile("cp.async.wait_group 0;" ::: "memory");
    __syncthreads();

    // ---- Q fragments from staging ----
    uint32_t qah[4][4], qal[4][4];
    {
        uint32_t aq = sbase + QSTG + (rg * 16 + rselA) * 144 + cselA;
#pragma unroll
        for (int s = 0; s < 4; s++) {
            ldmx4(qah[s][0], qah[s][1], qah[s][2], qah[s][3], aq + s * 32);
            ldmx4(qal[s][0], qal[s][1], qal[s][2], qal[s][3], aq + 9216 + s * 32);
        }
    }
    __syncthreads();   // frags read; buf1 free for tile-1 prefetch

    float oD[8][4];
#pragma unroll
    for (int j = 0; j < 8; j++)
#pragma unroll
        for (int qq = 0; qq < 4; qq++) oD[j][qq] = 0.f;
    float lsum0 = 0.f, lsum1 = 0.f;

    for (int tt = 0; tt < 32; tt++) {
        const uint32_t cur = sbase + (tt & 1) * BUFSZ;

        if (tt < 31) {
            uint32_t nxt = sbase + ((tt + 1) & 1) * BUFSZ;
            int tn = tt + 1;
#pragma unroll
            for (int i = 0; i < 4; i++) {
                int idx = tid + i * 256;
                int rk = idx >> 3, ck = idx & 7;
                cp16(nxt + KH_OFF + rk * 144 + ck * 16,
                     &khg[(size_t)(tn * 128 + rk) * 8 + ck]);
                int rv = idx >> 4, cv = idx & 15;
                cp16(nxt + VH_OFF + rv * 272 + cv * 16,
                     &vhg[(size_t)rv * 512 + tn * 16 + cv]);
            }
            asm volatile("cp.async.commit_group;" ::: "memory");
        }

        // ---- S = Q K^T over this warp's 64 keys (fp16 x2) ----
        float sD[8][4];
#pragma unroll
        for (int j = 0; j < 8; j++)
#pragma unroll
            for (int qq = 0; qq < 4; qq++) sD[j][qq] = 0.f;

        const uint32_t kb = cur + KH_OFF + (kh * 64 + rselB) * 144 + cselB;
#pragma unroll
        for (int s = 0; s < 4; s++) {
#pragma unroll
            for (int J = 0; J < 4; J++) {
                uint32_t b0, b1, b2, b3;
                ldmx4(b0, b1, b2, b3, kb + J * (16 * 144) + s * 32);
                mma_f16(sD[2 * J], qah[s][0], qah[s][1], qah[s][2], qah[s][3], b0, b1);
                mma_f16(sD[2 * J], qal[s][0], qal[s][1], qal[s][2], qal[s][3], b0, b1);
                mma_f16(sD[2 * J + 1], qah[s][0], qah[s][1], qah[s][2], qah[s][3], b2, b3);
                mma_f16(sD[2 * J + 1], qal[s][0], qal[s][1], qal[s][2], qal[s][3], b2, b3);
            }
        }

        // ---- exp(S - 8), pack P fragments ----
        uint32_t pa[4][4];
#pragma unroll
        for (int j = 0; j < 8; j++) {
            float p00 = __expf(sD[j][0] - SOFTMAX_SHIFT);
            float p01 = __expf(sD[j][1] - SOFTMAX_SHIFT);
            float p10 = __expf(sD[j][2] - SOFTMAX_SHIFT);
            float p11 = __expf(sD[j][3] - SOFTMAX_SHIFT);
            lsum0 += p00 + p01;
            lsum1 += p10 + p11;
            int c = j >> 1, hi = (j & 1) << 1;
            pa[c][hi + 0] = pack_h2(p00, p01);
            pa[c][hi + 1] = pack_h2(p10, p11);
        }

        // ---- O += P V over this warp's 64 keys ----
        const uint32_t vb = cur + VH_OFF + rselB * 272 + cselB + kh * 128;
#pragma unroll
        for (int c = 0; c < 4; c++) {
#pragma unroll
            for (int J = 0; J < 4; J++) {
                uint32_t v0, v1, v2, v3;
                ldmx4(v0, v1, v2, v3, vb + J * (16 * 272) + c * 32);
                mma_f16(oD[2 * J], pa[c][0], pa[c][1], pa[c][2], pa[c][3], v0, v1);
                mma_f16(oD[2 * J + 1], pa[c][0], pa[c][1], pa[c][2], pa[c][3], v2, v3);
            }
        }

        asm volatile("cp.async.wait_group 0;" ::: "memory");
        __syncthreads();
    }

    // ---- reduce row sums within quad ----
    lsum0 += __shfl_xor_sync(0xffffffffu, lsum0, 1);
    lsum0 += __shfl_xor_sync(0xffffffffu, lsum0, 2);
    lsum1 += __shfl_xor_sync(0xffffffffu, lsum1, 1);
    lsum1 += __shfl_xor_sync(0xffffffffu, lsum1, 2);

    // ---- cross-pair combine: kh=1 publishes, kh=0 sums + normalizes ----
    float* obuf = (float*)smem;              // 64 x 65 (buf0 region)
    float* lbuf = (float*)(smem + 16960);    // 64 floats
    float* tr = (float*)(smem + BUFSZ);      // 64 x 65 (buf1 region)

    if (kh == 1) {
#pragma unroll
        for (int j = 0; j < 8; j++) {
            int c0 = 8 * j + 2 * t;
            obuf[rowA * 65 + c0] = oD[j][0];
            obuf[rowA * 65 + c0 + 1] = oD[j][1];
            obuf[(rowA + 8) * 65 + c0] = oD[j][2];
            obuf[(rowA + 8) * 65 + c0 + 1] = oD[j][3];
        }
        if (t == 0) {
            lbuf[rowA] = lsum0;
            lbuf[rowA + 8] = lsum1;
        }
    }
    __syncthreads();
    if (kh == 0) {
        const float inv0 = 1.f / (lsum0 + lbuf[rowA]);
        const float inv1 = 1.f / (lsum1 + lbuf[rowA + 8]);
#pragma unroll
        for (int j = 0; j < 8; j++) {
            int c0 = 8 * j + 2 * t;
            tr[c0 * 65 + rowA] = (oD[j][0] + obuf[rowA * 65 + c0]) * inv0;
            tr[(c0 + 1) * 65 + rowA] = (oD[j][1] + obuf[rowA * 65 + c0 + 1]) * inv0;
            tr[c0 * 65 + rowA + 8] = (oD[j][2] + obuf[(rowA + 8) * 65 + c0]) * inv1;
            tr[(c0 + 1) * 65 + rowA + 8] = (oD[j][3] + obuf[(rowA + 8) * 65 + c0 + 1]) * inv1;
        }
    }
    __syncthreads();

    const float* gb = g_G + (size_t)b * 64 * NPIX + m0;
    const float* sb2 = g_GS + b * NPIX + m0;
    float* ob = out + (size_t)b * (CCH * NPIX) + m0;
    for (int i = tid; i < 4096; i += 256) {
        int d = i >> 6, m = i & 63;
        ob[(size_t)d * NPIX + m] = tr[d * 65 + m] * gb[(size_t)d * NPIX + m] * sb2[m];
    }
}

extern "C" void kernel_launch(void* const* d_in, const int* in_sizes, int n_in,
                              void* d_out, int out_size) {
    const float* x    = (const float*)d_in[0];
    const float* mask = (const float*)d_in[1];
    const unsigned int* flags = (const unsigned int*)d_in[2];
    const float* Wq = (const float*)d_in[3];
    const float* bq = (const float*)d_in[4];
    const float* Wk = (const float*)d_in[5];
    const float* bk = (const float*)d_in[6];
    const float* Wv = (const float*)d_in[7];
    const float* bv = (const float*)d_in[8];
    const float* Wg = (const float*)d_in[9];
    const float* bg = (const float*)d_in[10];
    const float* W1 = (const float*)d_in[11];
    const float* b1 = (const float*)d_in[12];
    const float* W2 = (const float*)d_in[13];
    const float* b2 = (const float*)d_in[14];
    float* out = (float*)d_out;

    cudaFuncSetAttribute(attn_kernel, cudaFuncAttributeMaxDynamicSharedMemorySize, SMEM_ATTN);
    cudaFuncSetAttribute(proj_mma, cudaFuncAttributeMaxDynamicSharedMemorySize, PROJ_SMEM);

    prep_kernel<<<128, 256>>>(Wq, bq, Wk, bk, Wv, bv, Wg, bg, W1, b1);
    proj_mma<<<dim3(32, 8), 256, PROJ_SMEM>>>(x, mask, flags, W2, b2);
    transpose_qk<<<dim3(64, 3, 8), 256>>>(flags);
    attn_kernel<<<dim3(64, 8), 256, SMEM_ATTN>>>(x, flags, out);
}

// round 11
// speedup vs baseline: 1.0817x; 1.0817x over previous
#include <cuda_runtime.h>
#include <cuda_fp16.h>
#include <cstdint>

#define NB 8
#define NPIX 4096
#define CCH 64

// ---------------- scratch (no allocation allowed) ----------------
// everything channel-major [b][c][n]; consumed directly via ldmatrix(.trans)
__device__ __align__(16) __half g_QhT[NB * CCH * NPIX];
__device__ __align__(16) __half g_QlT[NB * CCH * NPIX];
__device__ __align__(16) __half g_KhT[NB * CCH * NPIX];
__device__ __align__(16) __half g_Vh[NB * CCH * NPIX];
__device__ float g_G[NB * CCH * NPIX];    // sigmoid gate [b][c][m]
__device__ float g_GS[NB * NPIX];         // gate strength [b][m]
// packed weights: rows 0-63 Wq, 64-127 Wk, 128-191 Wv, 192-255 Wg, 256-511 W1
__device__ __align__(16) __half g_Wh[512 * 64];
__device__ __align__(16) __half g_Wl[512 * 64];
__device__ float g_bias[512];

// ---------------- weight prep kernel ----------------
__global__ __launch_bounds__(256) void prep_kernel(
    const float* __restrict__ Wq, const float* __restrict__ bq,
    const float* __restrict__ Wk, const float* __restrict__ bk,
    const float* __restrict__ Wv, const float* __restrict__ bv,
    const float* __restrict__ Wg, const float* __restrict__ bg,
    const float* __restrict__ W1, const float* __restrict__ b1) {
    int idx = blockIdx.x * 256 + threadIdx.x;   // 0..32767
    int row = idx >> 6, c = idx & 63;
    float w;
    if (row < 64)       w = Wq[row * 64 + c];
    else if (row < 128) w = Wk[(row - 64) * 64 + c];
    else if (row < 192) w = Wv[(row - 128) * 64 + c];
    else if (row < 256) w = Wg[(row - 192) * 64 + c];
    else                w = W1[(row - 256) * 64 + c];
    __half h = __float2half(w);
    g_Wh[idx] = h;
    g_Wl[idx] = __float2half(w - __half2float(h));
    if (c == 0) {
        float bv_;
        if (row < 64)       bv_ = bq[row];
        else if (row < 128) bv_ = bk[row - 64];
        else if (row < 192) bv_ = bv[row - 128];
        else if (row < 256) bv_ = bg[row - 192];
        else                bv_ = b1[row - 256];
        g_bias[row] = bv_;
    }
}

// ---------------- mma helpers ----------------
__device__ __forceinline__ void mma_f16(float* d, uint32_t a0, uint32_t a1,
                                        uint32_t a2, uint32_t a3,
                                        uint32_t b0, uint32_t b1) {
    asm volatile(
        "mma.sync.aligned.m16n8k16.row.col.f32.f16.f16.f32 "
        "{%0,%1,%2,%3}, {%4,%5,%6,%7}, {%8,%9}, {%0,%1,%2,%3};"
        : "+f"(d[0]), "+f"(d[1]), "+f"(d[2]), "+f"(d[3])
        : "r"(a0), "r"(a1), "r"(a2), "r"(a3), "r"(b0), "r"(b1));
}

__device__ __forceinline__ void ldmx4(uint32_t& r0, uint32_t& r1, uint32_t& r2,
                                      uint32_t& r3, uint32_t a) {
    asm volatile("ldmatrix.sync.aligned.m8n8.x4.shared.b16 {%0,%1,%2,%3}, [%4];"
                 : "=r"(r0), "=r"(r1), "=r"(r2), "=r"(r3) : "r"(a));
}

__device__ __forceinline__ void ldmx4t(uint32_t& r0, uint32_t& r1, uint32_t& r2,
                                       uint32_t& r3, uint32_t a) {
    asm volatile("ldmatrix.sync.aligned.m8n8.x4.trans.shared.b16 {%0,%1,%2,%3}, [%4];"
                 : "=r"(r0), "=r"(r1), "=r"(r2), "=r"(r3) : "r"(a));
}

__device__ __forceinline__ uint32_t pack_h2(float a, float b) {
    __half2 h = __floats2half2_rn(a, b);
    return *(uint32_t*)&h;
}

__device__ __forceinline__ void cp16(uint32_t s, const void* g) {
    asm volatile("cp.async.cg.shared.global [%0], [%1], 16;"
                 :: "r"(s), "l"(g) : "memory");
}

// ---------------- tensor-core projection kernel (unchanged) ----------------
#define SW_H 0
#define SW_L 73728
#define SX_H 147456
#define SX_L 164864
#define SBIAS 182272
#define SW2B 184320
#define SMVAL 185344
#define SGSP 185856
#define PROJ_SMEM 187904

__global__ __launch_bounds__(256, 1) void proj_mma(
    const float* __restrict__ x, const float* __restrict__ mask,
    const unsigned int* __restrict__ flags,
    const float* __restrict__ W2, const float* __restrict__ b2) {
    const int b = blockIdx.y;
    if (flags[b] == 0u) return;
    const int n0 = blockIdx.x * 128;

    extern __shared__ __align__(16) char sm[];
    uint32_t sb;
    asm("{ .reg .u64 t; cvta.to.shared.u64 t, %1; cvt.u32.u64 %0, t; }"
        : "=r"(sb) : "l"(sm));

    const int tid = threadIdx.x;
    const int wid = tid >> 5, lane = tid & 31;
    const int g = lane >> 2, t = lane & 3, q8 = lane & 7;

    for (int i = tid; i < 4096; i += 256) {
        int row = i >> 3, c8 = i & 7;
        *(uint4*)(sm + SW_H + row * 144 + c8 * 16) = ((const uint4*)g_Wh)[i];
        *(uint4*)(sm + SW_L + row * 144 + c8 * 16) = ((const uint4*)g_Wl)[i];
    }
    for (int i = tid; i < 2048; i += 256) {
        int c = i >> 5, n4 = i & 31;
        float4 xv = *(const float4*)(x + (size_t)b * (CCH * NPIX) +
                                     (size_t)c * NPIX + n0 + n4 * 4);
        __half h0 = __float2half(xv.x), h1 = __float2half(xv.y);
        __half h2 = __float2half(xv.z), h3 = __float2half(xv.w);
        uint2 hi, lo;
        {
            __half2 p0 = __halves2half2(h0, h1), p1 = __halves2half2(h2, h3);
            hi.x = *(uint32_t*)&p0; hi.y = *(uint32_t*)&p1;
        }
        lo.x = pack_h2(xv.x - __half2float(h0), xv.y - __half2float(h1));
        lo.y = pack_h2(xv.z - __half2float(h2), xv.w - __half2float(h3));
        *(uint2*)(sm + SX_H + c * 272 + n4 * 8) = hi;
        *(uint2*)(sm + SX_L + c * 272 + n4 * 8) = lo;
    }
    float* sBias = (float*)(sm + SBIAS);
    float* sW2 = (float*)(sm + SW2B);
    float* sMval = (float*)(sm + SMVAL);
    float* sGSp = (float*)(sm + SGSP);
    for (int i = tid; i < 512; i += 256) sBias[i] = g_bias[i];
    for (int i = tid; i < 256; i += 256) sW2[i] = W2[i];
    if (tid < 128) sMval[tid] = mask[b * NPIX + n0 + tid];
    __syncthreads();

    const uint32_t thrA = (uint32_t)(q8 + ((lane >> 3) & 1) * 8) * 144 +
                          ((lane >> 4) & 1) * 16;
    const uint32_t thrB = (uint32_t)(q8 + ((lane >> 3) & 1) * 8) * 272 +
                          ((lane >> 4) & 1) * 16;
    const float b2v = __ldg(b2);

    for (int nhalf = 0; nhalf < 2; nhalf++) {
        const int nb0 = nhalf * 64;
        for (int mpass = 0; mpass < 2; mpass++) {
            float d[2][8][4];
#pragma unroll
            for (int mt = 0; mt < 2; mt++)
#pragma unroll
                for (int nt = 0; nt < 8; nt++)
#pragma unroll
                    for (int q = 0; q < 4; q++) d[mt][nt][q] = 0.f;

            const uint32_t mrowbase = (uint32_t)(mpass * 256 + wid * 32) * 144;
#pragma unroll
            for (int pass = 0; pass < 3; pass++) {
                const uint32_t abase = sb + (pass < 2 ? SW_H : SW_L) + thrA + mrowbase;
                const uint32_t bbase = sb + (pass == 1 ? SX_L : SX_H) + thrB + nb0 * 2;
#pragma unroll
                for (int k = 0; k < 4; k++) {
                    uint32_t bf[4][4];
#pragma unroll
                    for (int ng = 0; ng < 4; ng++)
                        ldmx4t(bf[ng][0], bf[ng][1], bf[ng][2], bf[ng][3],
                               bbase + (uint32_t)k * (16 * 272) + ng * 32);
                    uint32_t af[2][4];
#pragma unroll
                    for (int mt = 0; mt < 2; mt++)
                        ldmx4(af[mt][0], af[mt][1], af[mt][2], af[mt][3],
                              abase + (uint32_t)mt * (16 * 144) + k * 32);
#pragma unroll
                    for (int mt = 0; mt < 2; mt++)
#pragma unroll
                        for (int ng = 0; ng < 4; ng++) {
                            mma_f16(d[mt][2 * ng], af[mt][0], af[mt][1], af[mt][2],
                                    af[mt][3], bf[ng][0], bf[ng][1]);
                            mma_f16(d[mt][2 * ng + 1], af[mt][0], af[mt][1], af[mt][2],
                                    af[mt][3], bf[ng][2], bf[ng][3]);
                        }
                }
            }

            if (mpass == 0) {
                const int sec = wid >> 1;
#pragma unroll
                for (int mt = 0; mt < 2; mt++) {
#pragma unroll
                    for (int ri = 0; ri < 2; ri++) {
                        const int ogl = wid * 32 + mt * 16 + g + ri * 8;
                        const int o = (wid & 1) * 32 + mt * 16 + g + ri * 8;
                        const float bias = sBias[ogl];
                        const size_t rowoff = (size_t)(b * 64 + o) * NPIX + n0;
#pragma unroll
                        for (int nt = 0; nt < 8; nt++) {
                            const int nl = nb0 + nt * 8 + 2 * t;
                            const float a0 = d[mt][nt][ri * 2 + 0];
                            const float a1 = d[mt][nt][ri * 2 + 1];
                            if (sec == 0 || sec == 1) {
                                const float m0 = sMval[nl], m1 = sMval[nl + 1];
                                const float v0 = bias + m0 * a0;
                                const float v1 = bias + m1 * a1;
                                __half h0 = __float2half(v0), h1 = __float2half(v1);
                                uint32_t hi = *(uint32_t*)&h0 |
                                              ((uint32_t)*(uint16_t*)&h1 << 16);
                                uint32_t lo = pack_h2(v0 - __half2float(h0),
                                                      v1 - __half2float(h1));
                                if (sec == 0) {
                                    *(uint32_t*)(g_QhT + rowoff + nl) = hi;
                                    *(uint32_t*)(g_QlT + rowoff + nl) = lo;
                                } else {
                                    *(uint32_t*)(g_KhT + rowoff + nl) = hi;
                                }
                            } else if (sec == 2) {
                                const float v0 = bias + a0, v1 = bias + a1;
                                *(uint32_t*)(g_Vh + rowoff + nl) = pack_h2(v0, v1);
                            } else {
                                const float v0 = bias + a0, v1 = bias + a1;
                                float2 gg;
                                gg.x = 1.f / (1.f + __expf(-v0));
                                gg.y = 1.f / (1.f + __expf(-v1));
                                *(float2*)(g_G + rowoff + nl) = gg;
                            }
                        }
                    }
                }
            } else {
                float gsp[16];
#pragma unroll
                for (int i = 0; i < 16; i++) gsp[i] = 0.f;
#pragma unroll
                for (int mt = 0; mt < 2; mt++) {
#pragma unroll
                    for (int ri = 0; ri < 2; ri++) {
                        const int o = wid * 32 + mt * 16 + g + ri * 8;
                        const float bias = sBias[256 + o];
                        const float w2v = sW2[o];
#pragma unroll
                        for (int nt = 0; nt < 8; nt++) {
                            float h0 = bias + d[mt][nt][ri * 2 + 0];
                            float h1 = bias + d[mt][nt][ri * 2 + 1];
                            gsp[nt * 2 + 0] += w2v * fmaxf(h0, 0.f);
                            gsp[nt * 2 + 1] += w2v * fmaxf(h1, 0.f);
                        }
                    }
                }
#pragma unroll
                for (int off = 4; off < 32; off <<= 1)
#pragma unroll
                    for (int i = 0; i < 16; i++)
                        gsp[i] += __shfl_xor_sync(0xffffffffu, gsp[i], off);
                if (lane < 4) {
#pragma unroll
                    for (int nt = 0; nt < 8; nt++) {
                        sGSp[wid * 64 + nt * 8 + 2 * lane + 0] = gsp[nt * 2 + 0];
                        sGSp[wid * 64 + nt * 8 + 2 * lane + 1] = gsp[nt * 2 + 1];
                    }
                }
                __syncthreads();
                if (tid < 64) {
                    float s = b2v;
#pragma unroll
                    for (int w = 0; w < 8; w++) s += sGSp[w * 64 + tid];
                    g_GS[b * NPIX + n0 + nb0 + tid] = 1.f / (1.f + __expf(-s));
                }
                __syncthreads();
            }
        }
    }
}

// ---------------- fp16 flash attention: BM=128, 3-stage pipeline,
//                  trans-fragments straight from channel-major ----------
#define KOFF 0
#define VOFF 17408
#define ABUFSZ 34816
#define QH_OFF (3 * ABUFSZ)            // 104448
#define QL_OFF (QH_OFF + 17408)        // 121856
#define SMEM_ATTN (QL_OFF + 17408)     // 139264
#define SOFTMAX_SHIFT 8.0f

__global__ __launch_bounds__(256, 1) void attn_kernel(
    const float* __restrict__ x, const unsigned int* __restrict__ flags,
    float* __restrict__ out) {
    const int b = blockIdx.y;
    const int m0 = blockIdx.x * 128;
    const int tid = threadIdx.x;

    if (flags[b] == 0u) {
        const float* xb = x + (size_t)b * (CCH * NPIX) + m0;
        float* ob = out + (size_t)b * (CCH * NPIX) + m0;
        for (int i = tid; i < 8192; i += 256) {
            int d = i >> 7, m = i & 127;
            ob[(size_t)d * NPIX + m] = xb[(size_t)d * NPIX + m];
        }
        return;
    }

    extern __shared__ __align__(16) char smem[];
    uint32_t sbase;
    asm("{ .reg .u64 t; cvta.to.shared.u64 t, %1; cvt.u32.u64 %0, t; }"
        : "=r"(sbase) : "l"(smem));

    const int wid = tid >> 5, lane = tid & 31;
    const int g = lane >> 2, t = lane & 3, q8 = lane & 7;
    const int rowA = wid * 16 + g;

    // selector duality:
    //   plain-A / trans-B : rows by bit3, col-half by bit4
    const uint32_t rA = q8 + ((lane >> 3) & 1) * 8;
    const uint32_t cA = ((lane >> 4) & 1) * 16;
    //   plain-B / trans-A : rows by bit4, col-half by bit3
    const uint32_t rB = q8 + ((lane >> 4) & 1) * 8;
    const uint32_t cB = ((lane >> 3) & 1) * 16;

    const char* qh_g = (const char*)(g_QhT + (size_t)b * CCH * NPIX) + m0 * 2;
    const char* ql_g = (const char*)(g_QlT + (size_t)b * CCH * NPIX) + m0 * 2;
    const char* kh_g = (const char*)(g_KhT + (size_t)b * CCH * NPIX);
    const char* vh_g = (const char*)(g_Vh + (size_t)b * CCH * NPIX);

    // ---- prologue: Q (hi/lo) + tile0 as group g0; tile1 as group g1 ----
#pragma unroll
    for (int i = 0; i < 4; i++) {
        int idx = tid + i * 256;           // 0..1023
        int row = idx >> 4, c16 = idx & 15;
        cp16(sbase + QH_OFF + row * 272 + c16 * 16, qh_g + row * 8192 + c16 * 16);
        cp16(sbase + QL_OFF + row * 272 + c16 * 16, ql_g + row * 8192 + c16 * 16);
        cp16(sbase + KOFF + row * 272 + c16 * 16, kh_g + row * 8192 + c16 * 16);
        cp16(sbase + VOFF + row * 272 + c16 * 16, vh_g + row * 8192 + c16 * 16);
    }
    asm volatile("cp.async.commit_group;" ::: "memory");
#pragma unroll
    for (int i = 0; i < 4; i++) {
        int idx = tid + i * 256;
        int row = idx >> 4, c16 = idx & 15;
        cp16(sbase + ABUFSZ + KOFF + row * 272 + c16 * 16,
             kh_g + row * 8192 + 256 + c16 * 16);
        cp16(sbase + ABUFSZ + VOFF + row * 272 + c16 * 16,
             vh_g + row * 8192 + 256 + c16 * 16);
    }
    asm volatile("cp.async.commit_group;" ::: "memory");
    asm volatile("cp.async.wait_group 1;" ::: "memory");
    __syncthreads();

    // ---- Q A-fragments via ldmatrix.trans (trans-A selectors) ----
    uint32_t qah[4][4], qal[4][4];
#pragma unroll
    for (int s = 0; s < 4; s++) {
        uint32_t qa = sbase + QH_OFF + (s * 16 + rB) * 272 + wid * 32 + cB;
        ldmx4t(qah[s][0], qah[s][1], qah[s][2], qah[s][3], qa);
        ldmx4t(qal[s][0], qal[s][1], qal[s][2], qal[s][3], qa + (QL_OFF - QH_OFF));
    }

    float oD[8][4];
#pragma unroll
    for (int j = 0; j < 8; j++)
#pragma unroll
        for (int qq = 0; qq < 4; qq++) oD[j][qq] = 0.f;
    float lsum0 = 0.f, lsum1 = 0.f;

    for (int tt = 0; tt < 32; tt++) {
        // own tt-copies done (2-tile pipeline slack)
        if (tt < 31) { asm volatile("cp.async.wait_group 1;" ::: "memory"); }
        else         { asm volatile("cp.async.wait_group 0;" ::: "memory"); }
        __syncthreads();   // everyone's tt copies visible; buf[(tt+2)%3] readers done

        if (tt + 2 < 32) {
            uint32_t nxt = sbase + ((tt + 2) % 3) * ABUFSZ;
            int nb = (tt + 2) * 256;
#pragma unroll
            for (int i = 0; i < 4; i++) {
                int idx = tid + i * 256;
                int row = idx >> 4, c16 = idx & 15;
                cp16(nxt + KOFF + row * 272 + c16 * 16,
                     kh_g + row * 8192 + nb + c16 * 16);
                cp16(nxt + VOFF + row * 272 + c16 * 16,
                     vh_g + row * 8192 + nb + c16 * 16);
            }
            asm volatile("cp.async.commit_group;" ::: "memory");
        }

        const uint32_t cur = sbase + (tt % 3) * ABUFSZ;

        // ---- S = Q K^T (fp16 x2), K B-frags via ldmatrix.trans ----
        float sD[16][4];
#pragma unroll
        for (int j = 0; j < 16; j++)
#pragma unroll
            for (int qq = 0; qq < 4; qq++) sD[j][qq] = 0.f;

#pragma unroll
        for (int s = 0; s < 4; s++) {
            const uint32_t kb = cur + KOFF + (s * 16 + rA) * 272 + cA;
#pragma unroll
            for (int J = 0; J < 8; J++) {
                uint32_t b0, b1, b2, b3;
                ldmx4t(b0, b1, b2, b3, kb + J * 32);
                mma_f16(sD[2 * J], qah[s][0], qah[s][1], qah[s][2], qah[s][3], b0, b1);
                mma_f16(sD[2 * J], qal[s][0], qal[s][1], qal[s][2], qal[s][3], b0, b1);
                mma_f16(sD[2 * J + 1], qah[s][0], qah[s][1], qah[s][2], qah[s][3], b2, b3);
                mma_f16(sD[2 * J + 1], qal[s][0], qal[s][1], qal[s][2], qal[s][3], b2, b3);
            }
        }

        // ---- exp(S - 8), pack P fragments in registers ----
        uint32_t pa[8][4];
#pragma unroll
        for (int j = 0; j < 16; j++) {
            float p00 = __expf(sD[j][0] - SOFTMAX_SHIFT);
            float p01 = __expf(sD[j][1] - SOFTMAX_SHIFT);
            float p10 = __expf(sD[j][2] - SOFTMAX_SHIFT);
            float p11 = __expf(sD[j][3] - SOFTMAX_SHIFT);
            lsum0 += p00 + p01;
            lsum1 += p10 + p11;
            int c = j >> 1, hi = (j & 1) << 1;
            pa[c][hi + 0] = pack_h2(p00, p01);
            pa[c][hi + 1] = pack_h2(p10, p11);
        }

        // ---- O += P V, V B-frags plain ldmatrix from [d][n] ----
        const uint32_t vb = cur + VOFF + rB * 272 + cB;
#pragma unroll
        for (int c = 0; c < 8; c++) {
#pragma unroll
            for (int J = 0; J < 4; J++) {
                uint32_t v0, v1, v2, v3;
                ldmx4(v0, v1, v2, v3, vb + J * (16 * 272) + c * 32);
                mma_f16(oD[2 * J], pa[c][0], pa[c][1], pa[c][2], pa[c][3], v0, v1);
                mma_f16(oD[2 * J + 1], pa[c][0], pa[c][1], pa[c][2], pa[c][3], v2, v3);
            }
        }
    }

    // ---- reduce row sums across the quad ----
    lsum0 += __shfl_xor_sync(0xffffffffu, lsum0, 1);
    lsum0 += __shfl_xor_sync(0xffffffffu, lsum0, 2);
    lsum1 += __shfl_xor_sync(0xffffffffu, lsum1, 1);
    lsum1 += __shfl_xor_sync(0xffffffffu, lsum1, 2);
    const float inv0 = 1.f / lsum0, inv1 = 1.f / lsum1;

    // ---- normalize + transpose to [d][m] (buf0 region: tile31 was in buf2/1)
    float* tr = (float*)smem;   // 64 x 129 floats = 33 KB (tile 31 lives in buf2)
#pragma unroll
    for (int j = 0; j < 8; j++) {
        int c0 = 8 * j + 2 * t;
        tr[c0 * 129 + rowA] = oD[j][0] * inv0;
        tr[(c0 + 1) * 129 + rowA] = oD[j][1] * inv0;
        tr[c0 * 129 + rowA + 8] = oD[j][2] * inv1;
        tr[(c0 + 1) * 129 + rowA + 8] = oD[j][3] * inv1;
    }
    __syncthreads();

    const float* gb = g_G + (size_t)b * 64 * NPIX + m0;
    const float* sb2 = g_GS + b * NPIX + m0;
    float* ob = out + (size_t)b * (CCH * NPIX) + m0;
    for (int i = tid; i < 8192; i += 256) {
        int d = i >> 7, m = i & 127;
        ob[(size_t)d * NPIX + m] = tr[d * 129 + m] * gb[(size_t)d * NPIX + m] * sb2[m];
    }
}

extern "C" void kernel_launch(void* const* d_in, const int* in_sizes, int n_in,
                              void* d_out, int out_size) {
    const float* x    = (const float*)d_in[0];
    const float* mask = (const float*)d_in[1];
    const unsigned int* flags = (const unsigned int*)d_in[2];
    const float* Wq = (const float*)d_in[3];
    const float* bq = (const float*)d_in[4];
    const float* Wk = (const float*)d_in[5];
    const float* bk = (const float*)d_in[6];
    const float* Wv = (const float*)d_in[7];
    const float* bv = (const float*)d_in[8];
    const float* Wg = (const float*)d_in[9];
    const float* bg = (const float*)d_in[10];
    const float* W1 = (const float*)d_in[11];
    const float* b1 = (const float*)d_in[12];
    const float* W2 = (const float*)d_in[13];
    const float* b2 = (const float*)d_in[14];
    float* out = (float*)d_out;

    cudaFuncSetAttribute(attn_kernel, cudaFuncAttributeMaxDynamicSharedMemorySize, SMEM_ATTN);
    cudaFuncSetAttribute(proj_mma, cudaFuncAttributeMaxDynamicSharedMemorySize, PROJ_SMEM);

    prep_kernel<<<128, 256>>>(Wq, bq, Wk, bk, Wv, bv, Wg, bg, W1, b1);
    proj_mma<<<dim3(32, 8), 256, PROJ_SMEM>>>(x, mask, flags, W2, b2);
    attn_kernel<<<dim3(32, 8), 256, SMEM_ATTN>>>(x, flags, out);
}

// round 12
// speedup vs baseline: 1.2383x; 1.1447x over previous
#include <cuda_runtime.h>
#include <cuda_fp16.h>
#include <cstdint>

#define NB 8
#define NPIX 4096
#define CCH 64

// ---------------- scratch (no allocation allowed) ----------------
// everything channel-major [b][c][n]; consumed directly via ldmatrix(.trans)
__device__ __align__(16) __half g_QhT[NB * CCH * NPIX];
__device__ __align__(16) __half g_KhT[NB * CCH * NPIX];
__device__ __align__(16) __half g_Vh[NB * CCH * NPIX];
__device__ float g_G[NB * CCH * NPIX];    // sigmoid gate [b][c][m]
__device__ float g_GS[NB * NPIX];         // gate strength [b][m]
// packed weights: rows 0-63 Wq, 64-127 Wk, 128-191 Wv, 192-255 Wg, 256-511 W1
__device__ __align__(16) __half g_Wh[512 * 64];
__device__ __align__(16) __half g_Wl[512 * 64];
__device__ float g_bias[512];

// ---------------- weight prep kernel ----------------
__global__ __launch_bounds__(256) void prep_kernel(
    const float* __restrict__ Wq, const float* __restrict__ bq,
    const float* __restrict__ Wk, const float* __restrict__ bk,
    const float* __restrict__ Wv, const float* __restrict__ bv,
    const float* __restrict__ Wg, const float* __restrict__ bg,
    const float* __restrict__ W1, const float* __restrict__ b1) {
    int idx = blockIdx.x * 256 + threadIdx.x;   // 0..32767
    int row = idx >> 6, c = idx & 63;
    float w;
    if (row < 64)       w = Wq[row * 64 + c];
    else if (row < 128) w = Wk[(row - 64) * 64 + c];
    else if (row < 192) w = Wv[(row - 128) * 64 + c];
    else if (row < 256) w = Wg[(row - 192) * 64 + c];
    else                w = W1[(row - 256) * 64 + c];
    __half h = __float2half(w);
    g_Wh[idx] = h;
    g_Wl[idx] = __float2half(w - __half2float(h));
    if (c == 0) {
        float bv_;
        if (row < 64)       bv_ = bq[row];
        else if (row < 128) bv_ = bk[row - 64];
        else if (row < 192) bv_ = bv[row - 128];
        else if (row < 256) bv_ = bg[row - 192];
        else                bv_ = b1[row - 256];
        g_bias[row] = bv_;
    }
}

// ---------------- mma helpers ----------------
__device__ __forceinline__ void mma_f16(float* d, uint32_t a0, uint32_t a1,
                                        uint32_t a2, uint32_t a3,
                                        uint32_t b0, uint32_t b1) {
    asm volatile(
        "mma.sync.aligned.m16n8k16.row.col.f32.f16.f16.f32 "
        "{%0,%1,%2,%3}, {%4,%5,%6,%7}, {%8,%9}, {%0,%1,%2,%3};"
        : "+f"(d[0]), "+f"(d[1]), "+f"(d[2]), "+f"(d[3])
        : "r"(a0), "r"(a1), "r"(a2), "r"(a3), "r"(b0), "r"(b1));
}

__device__ __forceinline__ void ldmx4(uint32_t& r0, uint32_t& r1, uint32_t& r2,
                                      uint32_t& r3, uint32_t a) {
    asm volatile("ldmatrix.sync.aligned.m8n8.x4.shared.b16 {%0,%1,%2,%3}, [%4];"
                 : "=r"(r0), "=r"(r1), "=r"(r2), "=r"(r3) : "r"(a));
}

__device__ __forceinline__ void ldmx4t(uint32_t& r0, uint32_t& r1, uint32_t& r2,
                                       uint32_t& r3, uint32_t a) {
    asm volatile("ldmatrix.sync.aligned.m8n8.x4.trans.shared.b16 {%0,%1,%2,%3}, [%4];"
                 : "=r"(r0), "=r"(r1), "=r"(r2), "=r"(r3) : "r"(a));
}

__device__ __forceinline__ uint32_t pack_h2(float a, float b) {
    __half2 h = __floats2half2_rn(a, b);
    return *(uint32_t*)&h;
}

__device__ __forceinline__ void cp16(uint32_t s, const void* g) {
    asm volatile("cp.async.cg.shared.global [%0], [%1], 16;"
                 :: "r"(s), "l"(g) : "memory");
}

// ---------------- tensor-core projection kernel ----------------
#define SW_H 0
#define SW_L 73728
#define SX_H 147456
#define SX_L 164864
#define SBIAS 182272
#define SW2B 184320
#define SMVAL 185344
#define SGSP 185856
#define PROJ_SMEM 187904

__global__ __launch_bounds__(256, 1) void proj_mma(
    const float* __restrict__ x, const float* __restrict__ mask,
    const unsigned int* __restrict__ flags,
    const float* __restrict__ W2, const float* __restrict__ b2) {
    const int b = blockIdx.y;
    if (flags[b] == 0u) return;
    const int n0 = blockIdx.x * 128;

    extern __shared__ __align__(16) char sm[];
    uint32_t sb;
    asm("{ .reg .u64 t; cvta.to.shared.u64 t, %1; cvt.u32.u64 %0, t; }"
        : "=r"(sb) : "l"(sm));

    const int tid = threadIdx.x;
    const int wid = tid >> 5, lane = tid & 31;
    const int g = lane >> 2, t = lane & 3, q8 = lane & 7;

    for (int i = tid; i < 4096; i += 256) {
        int row = i >> 3, c8 = i & 7;
        *(uint4*)(sm + SW_H + row * 144 + c8 * 16) = ((const uint4*)g_Wh)[i];
        *(uint4*)(sm + SW_L + row * 144 + c8 * 16) = ((const uint4*)g_Wl)[i];
    }
    for (int i = tid; i < 2048; i += 256) {
        int c = i >> 5, n4 = i & 31;
        float4 xv = *(const float4*)(x + (size_t)b * (CCH * NPIX) +
                                     (size_t)c * NPIX + n0 + n4 * 4);
        __half h0 = __float2half(xv.x), h1 = __float2half(xv.y);
        __half h2 = __float2half(xv.z), h3 = __float2half(xv.w);
        uint2 hi, lo;
        {
            __half2 p0 = __halves2half2(h0, h1), p1 = __halves2half2(h2, h3);
            hi.x = *(uint32_t*)&p0; hi.y = *(uint32_t*)&p1;
        }
        lo.x = pack_h2(xv.x - __half2float(h0), xv.y - __half2float(h1));
        lo.y = pack_h2(xv.z - __half2float(h2), xv.w - __half2float(h3));
        *(uint2*)(sm + SX_H + c * 272 + n4 * 8) = hi;
        *(uint2*)(sm + SX_L + c * 272 + n4 * 8) = lo;
    }
    float* sBias = (float*)(sm + SBIAS);
    float* sW2 = (float*)(sm + SW2B);
    float* sMval = (float*)(sm + SMVAL);
    float* sGSp = (float*)(sm + SGSP);
    for (int i = tid; i < 512; i += 256) sBias[i] = g_bias[i];
    for (int i = tid; i < 256; i += 256) sW2[i] = W2[i];
    if (tid < 128) sMval[tid] = mask[b * NPIX + n0 + tid];
    __syncthreads();

    const uint32_t thrA = (uint32_t)(q8 + ((lane >> 3) & 1) * 8) * 144 +
                          ((lane >> 4) & 1) * 16;
    const uint32_t thrB = (uint32_t)(q8 + ((lane >> 3) & 1) * 8) * 272 +
                          ((lane >> 4) & 1) * 16;
    const float b2v = __ldg(b2);

    for (int nhalf = 0; nhalf < 2; nhalf++) {
        const int nb0 = nhalf * 64;
        for (int mpass = 0; mpass < 2; mpass++) {
            float d[2][8][4];
#pragma unroll
            for (int mt = 0; mt < 2; mt++)
#pragma unroll
                for (int nt = 0; nt < 8; nt++)
#pragma unroll
                    for (int q = 0; q < 4; q++) d[mt][nt][q] = 0.f;

            const uint32_t mrowbase = (uint32_t)(mpass * 256 + wid * 32) * 144;
#pragma unroll
            for (int pass = 0; pass < 3; pass++) {
                const uint32_t abase = sb + (pass < 2 ? SW_H : SW_L) + thrA + mrowbase;
                const uint32_t bbase = sb + (pass == 1 ? SX_L : SX_H) + thrB + nb0 * 2;
#pragma unroll
                for (int k = 0; k < 4; k++) {
                    uint32_t bf[4][4];
#pragma unroll
                    for (int ng = 0; ng < 4; ng++)
                        ldmx4t(bf[ng][0], bf[ng][1], bf[ng][2], bf[ng][3],
                               bbase + (uint32_t)k * (16 * 272) + ng * 32);
                    uint32_t af[2][4];
#pragma unroll
                    for (int mt = 0; mt < 2; mt++)
                        ldmx4(af[mt][0], af[mt][1], af[mt][2], af[mt][3],
                              abase + (uint32_t)mt * (16 * 144) + k * 32);
#pragma unroll
                    for (int mt = 0; mt < 2; mt++)
#pragma unroll
                        for (int ng = 0; ng < 4; ng++) {
                            mma_f16(d[mt][2 * ng], af[mt][0], af[mt][1], af[mt][2],
                                    af[mt][3], bf[ng][0], bf[ng][1]);
                            mma_f16(d[mt][2 * ng + 1], af[mt][0], af[mt][1], af[mt][2],
                                    af[mt][3], bf[ng][2], bf[ng][3]);
                        }
                }
            }

            if (mpass == 0) {
                const int sec = wid >> 1;
#pragma unroll
                for (int mt = 0; mt < 2; mt++) {
#pragma unroll
                    for (int ri = 0; ri < 2; ri++) {
                        const int ogl = wid * 32 + mt * 16 + g + ri * 8;
                        const int o = (wid & 1) * 32 + mt * 16 + g + ri * 8;
                        const float bias = sBias[ogl];
                        const size_t rowoff = (size_t)(b * 64 + o) * NPIX + n0;
#pragma unroll
                        for (int nt = 0; nt < 8; nt++) {
                            const int nl = nb0 + nt * 8 + 2 * t;
                            const float a0 = d[mt][nt][ri * 2 + 0];
                            const float a1 = d[mt][nt][ri * 2 + 1];
                            if (sec == 0 || sec == 1) {
                                const float m0 = sMval[nl], m1 = sMval[nl + 1];
                                const float v0 = bias + m0 * a0;
                                const float v1 = bias + m1 * a1;
                                if (sec == 0) {
                                    *(uint32_t*)(g_QhT + rowoff + nl) = pack_h2(v0, v1);
                                } else {
                                    *(uint32_t*)(g_KhT + rowoff + nl) = pack_h2(v0, v1);
                                }
                            } else if (sec == 2) {
                                const float v0 = bias + a0, v1 = bias + a1;
                                *(uint32_t*)(g_Vh + rowoff + nl) = pack_h2(v0, v1);
                            } else {
                                const float v0 = bias + a0, v1 = bias + a1;
                                float2 gg;
                                gg.x = 1.f / (1.f + __expf(-v0));
                                gg.y = 1.f / (1.f + __expf(-v1));
                                *(float2*)(g_G + rowoff + nl) = gg;
                            }
                        }
                    }
                }
            } else {
                float gsp[16];
#pragma unroll
                for (int i = 0; i < 16; i++) gsp[i] = 0.f;
#pragma unroll
                for (int mt = 0; mt < 2; mt++) {
#pragma unroll
                    for (int ri = 0; ri < 2; ri++) {
                        const int o = wid * 32 + mt * 16 + g + ri * 8;
                        const float bias = sBias[256 + o];
                        const float w2v = sW2[o];
#pragma unroll
                        for (int nt = 0; nt < 8; nt++) {
                            float h0 = bias + d[mt][nt][ri * 2 + 0];
                            float h1 = bias + d[mt][nt][ri * 2 + 1];
                            gsp[nt * 2 + 0] += w2v * fmaxf(h0, 0.f);
                            gsp[nt * 2 + 1] += w2v * fmaxf(h1, 0.f);
                        }
                    }
                }
#pragma unroll
                for (int off = 4; off < 32; off <<= 1)
#pragma unroll
                    for (int i = 0; i < 16; i++)
                        gsp[i] += __shfl_xor_sync(0xffffffffu, gsp[i], off);
                if (lane < 4) {
#pragma unroll
                    for (int nt = 0; nt < 8; nt++) {
                        sGSp[wid * 64 + nt * 8 + 2 * lane + 0] = gsp[nt * 2 + 0];
                        sGSp[wid * 64 + nt * 8 + 2 * lane + 1] = gsp[nt * 2 + 1];
                    }
                }
                __syncthreads();
                if (tid < 64) {
                    float s = b2v;
#pragma unroll
                    for (int w = 0; w < 8; w++) s += sGSp[w * 64 + tid];
                    g_GS[b * NPIX + n0 + nb0 + tid] = 1.f / (1.f + __expf(-s));
                }
                __syncthreads();
            }
        }
    }
}

// ---------------- fp16 flash attention: BM=128, single-pass S, 3-stage ------
#define KOFF 0
#define VOFF 17408
#define ABUFSZ 34816
#define QH_OFF (3 * ABUFSZ)            // 104448
#define SMEM_ATTN (QH_OFF + 17408)     // 121856
#define SOFTMAX_SHIFT 8.0f

__global__ __launch_bounds__(256, 1) void attn_kernel(
    const float* __restrict__ x, const unsigned int* __restrict__ flags,
    float* __restrict__ out) {
    const int b = blockIdx.y;
    const int m0 = blockIdx.x * 128;
    const int tid = threadIdx.x;

    if (flags[b] == 0u) {
        const float* xb = x + (size_t)b * (CCH * NPIX) + m0;
        float* ob = out + (size_t)b * (CCH * NPIX) + m0;
        for (int i = tid; i < 8192; i += 256) {
            int d = i >> 7, m = i & 127;
            ob[(size_t)d * NPIX + m] = xb[(size_t)d * NPIX + m];
        }
        return;
    }

    extern __shared__ __align__(16) char smem[];
    uint32_t sbase;
    asm("{ .reg .u64 t; cvta.to.shared.u64 t, %1; cvt.u32.u64 %0, t; }"
        : "=r"(sbase) : "l"(smem));

    const int wid = tid >> 5, lane = tid & 31;
    const int g = lane >> 2, t = lane & 3, q8 = lane & 7;
    const int rowA = wid * 16 + g;

    //   plain-A / trans-B : rows by bit3, col-half by bit4
    const uint32_t rA = q8 + ((lane >> 3) & 1) * 8;
    const uint32_t cA = ((lane >> 4) & 1) * 16;
    //   plain-B / trans-A : rows by bit4, col-half by bit3
    const uint32_t rB = q8 + ((lane >> 4) & 1) * 8;
    const uint32_t cB = ((lane >> 3) & 1) * 16;

    const char* qh_g = (const char*)(g_QhT + (size_t)b * CCH * NPIX) + m0 * 2;
    const char* kh_g = (const char*)(g_KhT + (size_t)b * CCH * NPIX);
    const char* vh_g = (const char*)(g_Vh + (size_t)b * CCH * NPIX);

    // ---- prologue: Q + tile0 as group g0; tile1 as group g1 ----
#pragma unroll
    for (int i = 0; i < 4; i++) {
        int idx = tid + i * 256;           // 0..1023
        int row = idx >> 4, c16 = idx & 15;
        cp16(sbase + QH_OFF + row * 272 + c16 * 16, qh_g + row * 8192 + c16 * 16);
        cp16(sbase + KOFF + row * 272 + c16 * 16, kh_g + row * 8192 + c16 * 16);
        cp16(sbase + VOFF + row * 272 + c16 * 16, vh_g + row * 8192 + c16 * 16);
    }
    asm volatile("cp.async.commit_group;" ::: "memory");
#pragma unroll
    for (int i = 0; i < 4; i++) {
        int idx = tid + i * 256;
        int row = idx >> 4, c16 = idx & 15;
        cp16(sbase + ABUFSZ + KOFF + row * 272 + c16 * 16,
             kh_g + row * 8192 + 256 + c16 * 16);
        cp16(sbase + ABUFSZ + VOFF + row * 272 + c16 * 16,
             vh_g + row * 8192 + 256 + c16 * 16);
    }
    asm volatile("cp.async.commit_group;" ::: "memory");
    asm volatile("cp.async.wait_group 1;" ::: "memory");
    __syncthreads();

    // ---- Q A-fragments via ldmatrix.trans (trans-A selectors) ----
    uint32_t qah[4][4];
#pragma unroll
    for (int s = 0; s < 4; s++) {
        uint32_t qa = sbase + QH_OFF + (s * 16 + rB) * 272 + wid * 32 + cB;
        ldmx4t(qah[s][0], qah[s][1], qah[s][2], qah[s][3], qa);
    }

    float oD[8][4];
#pragma unroll
    for (int j = 0; j < 8; j++)
#pragma unroll
        for (int qq = 0; qq < 4; qq++) oD[j][qq] = 0.f;
    float lsum0 = 0.f, lsum1 = 0.f;

    for (int tt = 0; tt < 32; tt++) {
        if (tt < 31) { asm volatile("cp.async.wait_group 1;" ::: "memory"); }
        else         { asm volatile("cp.async.wait_group 0;" ::: "memory"); }
        __syncthreads();

        if (tt + 2 < 32) {
            uint32_t nxt = sbase + ((tt + 2) % 3) * ABUFSZ;
            int nb = (tt + 2) * 256;
#pragma unroll
            for (int i = 0; i < 4; i++) {
                int idx = tid + i * 256;
                int row = idx >> 4, c16 = idx & 15;
                cp16(nxt + KOFF + row * 272 + c16 * 16,
                     kh_g + row * 8192 + nb + c16 * 16);
                cp16(nxt + VOFF + row * 272 + c16 * 16,
                     vh_g + row * 8192 + nb + c16 * 16);
            }
            asm volatile("cp.async.commit_group;" ::: "memory");
        }

        const uint32_t cur = sbase + (tt % 3) * ABUFSZ;

        // ---- S = Q K^T (single-pass fp16), K B-frags via ldmatrix.trans ----
        float sD[16][4];
#pragma unroll
        for (int j = 0; j < 16; j++)
#pragma unroll
            for (int qq = 0; qq < 4; qq++) sD[j][qq] = 0.f;

#pragma unroll
        for (int s = 0; s < 4; s++) {
            const uint32_t kb = cur + KOFF + (s * 16 + rA) * 272 + cA;
#pragma unroll
            for (int J = 0; J < 8; J++) {
                uint32_t b0, b1, b2, b3;
                ldmx4t(b0, b1, b2, b3, kb + J * 32);
                mma_f16(sD[2 * J], qah[s][0], qah[s][1], qah[s][2], qah[s][3], b0, b1);
                mma_f16(sD[2 * J + 1], qah[s][0], qah[s][1], qah[s][2], qah[s][3], b2, b3);
            }
        }

        // ---- exp(S - 8), pack P fragments in registers ----
        uint32_t pa[8][4];
#pragma unroll
        for (int j = 0; j < 16; j++) {
            float p00 = __expf(sD[j][0] - SOFTMAX_SHIFT);
            float p01 = __expf(sD[j][1] - SOFTMAX_SHIFT);
            float p10 = __expf(sD[j][2] - SOFTMAX_SHIFT);
            float p11 = __expf(sD[j][3] - SOFTMAX_SHIFT);
            lsum0 += p00 + p01;
            lsum1 += p10 + p11;
            int c = j >> 1, hi = (j & 1) << 1;
            pa[c][hi + 0] = pack_h2(p00, p01);
            pa[c][hi + 1] = pack_h2(p10, p11);
        }

        // ---- O += P V, V B-frags plain ldmatrix from [d][n] ----
        const uint32_t vb = cur + VOFF + rB * 272 + cB;
#pragma unroll
        for (int c = 0; c < 8; c++) {
#pragma unroll
            for (int J = 0; J < 4; J++) {
                uint32_t v0, v1, v2, v3;
                ldmx4(v0, v1, v2, v3, vb + J * (16 * 272) + c * 32);
                mma_f16(oD[2 * J], pa[c][0], pa[c][1], pa[c][2], pa[c][3], v0, v1);
                mma_f16(oD[2 * J + 1], pa[c][0], pa[c][1], pa[c][2], pa[c][3], v2, v3);
            }
        }
    }

    // ---- reduce row sums across the quad ----
    lsum0 += __shfl_xor_sync(0xffffffffu, lsum0, 1);
    lsum0 += __shfl_xor_sync(0xffffffffu, lsum0, 2);
    lsum1 += __shfl_xor_sync(0xffffffffu, lsum1, 1);
    lsum1 += __shfl_xor_sync(0xffffffffu, lsum1, 2);
    const float inv0 = 1.f / lsum0, inv1 = 1.f / lsum1;

    // ---- normalize + transpose to [d][m] (buf0 region; tile31 in buf2) ----
    float* tr = (float*)smem;   // 64 x 129 floats = 33 KB
#pragma unroll
    for (int j = 0; j < 8; j++) {
        int c0 = 8 * j + 2 * t;
        tr[c0 * 129 + rowA] = oD[j][0] * inv0;
        tr[(c0 + 1) * 129 + rowA] = oD[j][1] * inv0;
        tr[c0 * 129 + rowA + 8] = oD[j][2] * inv1;
        tr[(c0 + 1) * 129 + rowA + 8] = oD[j][3] * inv1;
    }
    __syncthreads();

    const float* gb = g_G + (size_t)b * 64 * NPIX + m0;
    const float* sb2 = g_GS + b * NPIX + m0;
    float* ob = out + (size_t)b * (CCH * NPIX) + m0;
    for (int i = tid; i < 8192; i += 256) {
        int d = i >> 7, m = i & 127;
        ob[(size_t)d * NPIX + m] = tr[d * 129 + m] * gb[(size_t)d * NPIX + m] * sb2[m];
    }
}

extern "C" void kernel_launch(void* const* d_in, const int* in_sizes, int n_in,
                              void* d_out, int out_size) {
    const float* x    = (const float*)d_in[0];
    const float* mask = (const float*)d_in[1];
    const unsigned int* flags = (const unsigned int*)d_in[2];
    const float* Wq = (const float*)d_in[3];
    const float* bq = (const float*)d_in[4];
    const float* Wk = (const float*)d_in[5];
    const float* bk = (const float*)d_in[6];
    const float* Wv = (const float*)d_in[7];
    const float* bv = (const float*)d_in[8];
    const float* Wg = (const float*)d_in[9];
    const float* bg = (const float*)d_in[10];
    const float* W1 = (const float*)d_in[11];
    const float* b1 = (const float*)d_in[12];
    const float* W2 = (const float*)d_in[13];
    const float* b2 = (const float*)d_in[14];
    float* out = (float*)d_out;

    cudaFuncSetAttribute(attn_kernel, cudaFuncAttributeMaxDynamicSharedMemorySize, SMEM_ATTN);
    cudaFuncSetAttribute(proj_mma, cudaFuncAttributeMaxDynamicSharedMemorySize, PROJ_SMEM);

    prep_kernel<<<128, 256>>>(Wq, bq, Wk, bk, Wv, bv, Wg, bg, W1, b1);
    proj_mma<<<dim3(32, 8), 256, PROJ_SMEM>>>(x, mask, flags, W2, b2);
    attn_kernel<<<dim3(32, 8), 256, SMEM_ATTN>>>(x, flags, out);
}

// round 13
// speedup vs baseline: 1.3115x; 1.0591x over previous
#include <cuda_runtime.h>
#include <cuda_fp16.h>
#include <cstdint>

#define NB 8
#define NPIX 4096
#define CCH 64

// ---------------- scratch (no allocation allowed) ----------------
// everything channel-major [b][c][n]; consumed directly via ldmatrix(.trans)
__device__ __align__(16) __half g_QhT[NB * CCH * NPIX];
__device__ __align__(16) __half g_KhT[NB * CCH * NPIX];
__device__ __align__(16) __half g_Vh[NB * CCH * NPIX];
__device__ float g_G[NB * CCH * NPIX];    // sigmoid gate [b][c][m]
__device__ float g_GS[NB * NPIX];         // gate strength [b][m]

// ---------------- mma helpers ----------------
__device__ __forceinline__ void mma_f16(float* d, uint32_t a0, uint32_t a1,
                                        uint32_t a2, uint32_t a3,
                                        uint32_t b0, uint32_t b1) {
    asm volatile(
        "mma.sync.aligned.m16n8k16.row.col.f32.f16.f16.f32 "
        "{%0,%1,%2,%3}, {%4,%5,%6,%7}, {%8,%9}, {%0,%1,%2,%3};"
        : "+f"(d[0]), "+f"(d[1]), "+f"(d[2]), "+f"(d[3])
        : "r"(a0), "r"(a1), "r"(a2), "r"(a3), "r"(b0), "r"(b1));
}

__device__ __forceinline__ void ldmx4(uint32_t& r0, uint32_t& r1, uint32_t& r2,
                                      uint32_t& r3, uint32_t a) {
    asm volatile("ldmatrix.sync.aligned.m8n8.x4.shared.b16 {%0,%1,%2,%3}, [%4];"
                 : "=r"(r0), "=r"(r1), "=r"(r2), "=r"(r3) : "r"(a));
}

__device__ __forceinline__ void ldmx4t(uint32_t& r0, uint32_t& r1, uint32_t& r2,
                                       uint32_t& r3, uint32_t a) {
    asm volatile("ldmatrix.sync.aligned.m8n8.x4.trans.shared.b16 {%0,%1,%2,%3}, [%4];"
                 : "=r"(r0), "=r"(r1), "=r"(r2), "=r"(r3) : "r"(a));
}

__device__ __forceinline__ uint32_t pack_h2(float a, float b) {
    __half2 h = __floats2half2_rn(a, b);
    return *(uint32_t*)&h;
}

__device__ __forceinline__ uint32_t h2u(__half a, __half b) {
    __half2 p = __halves2half2(a, b);
    return *(uint32_t*)&p;
}

__device__ __forceinline__ uint32_t ex2_h2(uint32_t x) {
    uint32_t r;
    asm("ex2.approx.f16x2 %0, %1;" : "=r"(r) : "r"(x));
    return r;
}

__device__ __forceinline__ void cp16(uint32_t s, const void* g) {
    asm volatile("cp.async.cg.shared.global [%0], [%1], 16;"
                 :: "r"(s), "l"(g) : "memory");
}

// ---------------- tensor-core projection kernel (weights converted inline) --
#define SW_H 0
#define SW_L 73728
#define SX_H 147456
#define SX_L 164864
#define SBIAS 182272
#define SW2B 184320
#define SMVAL 185344
#define SGSP 185856
#define PROJ_SMEM 187904

__global__ __launch_bounds__(256, 1) void proj_mma(
    const float* __restrict__ x, const float* __restrict__ mask,
    const unsigned int* __restrict__ flags,
    const float* __restrict__ Wq, const float* __restrict__ bq,
    const float* __restrict__ Wk, const float* __restrict__ bk,
    const float* __restrict__ Wv, const float* __restrict__ bv,
    const float* __restrict__ Wg, const float* __restrict__ bg,
    const float* __restrict__ W1, const float* __restrict__ b1,
    const float* __restrict__ W2, const float* __restrict__ b2) {
    const int b = blockIdx.y;
    if (flags[b] == 0u) return;
    const int n0 = blockIdx.x * 128;

    extern __shared__ __align__(16) char sm[];
    uint32_t sb;
    asm("{ .reg .u64 t; cvta.to.shared.u64 t, %1; cvt.u32.u64 %0, t; }"
        : "=r"(sb) : "l"(sm));

    const int tid = threadIdx.x;
    const int wid = tid >> 5, lane = tid & 31;
    const int g = lane >> 2, t = lane & 3, q8 = lane & 7;

    // ---- stage weights: read fp32, split hi/lo inline ----
    for (int i = tid; i < 4096; i += 256) {
        int row = i >> 3, c8 = i & 7;
        const float* src;
        if (row < 64)       src = Wq + row * 64;
        else if (row < 128) src = Wk + (row - 64) * 64;
        else if (row < 192) src = Wv + (row - 128) * 64;
        else if (row < 256) src = Wg + (row - 192) * 64;
        else                src = W1 + (row - 256) * 64;
        float4 a = *(const float4*)(src + c8 * 8);
        float4 c = *(const float4*)(src + c8 * 8 + 4);
        __half h0 = __float2half(a.x), h1 = __float2half(a.y);
        __half h2 = __float2half(a.z), h3 = __float2half(a.w);
        __half h4 = __float2half(c.x), h5 = __float2half(c.y);
        __half h6 = __float2half(c.z), h7 = __float2half(c.w);
        uint4 hi4, lo4;
        hi4.x = h2u(h0, h1); hi4.y = h2u(h2, h3);
        hi4.z = h2u(h4, h5); hi4.w = h2u(h6, h7);
        lo4.x = pack_h2(a.x - __half2float(h0), a.y - __half2float(h1));
        lo4.y = pack_h2(a.z - __half2float(h2), a.w - __half2float(h3));
        lo4.z = pack_h2(c.x - __half2float(h4), c.y - __half2float(h5));
        lo4.w = pack_h2(c.z - __half2float(h6), c.w - __half2float(h7));
        *(uint4*)(sm + SW_H + row * 144 + c8 * 16) = hi4;
        *(uint4*)(sm + SW_L + row * 144 + c8 * 16) = lo4;
    }
    // ---- stage x tile [c][n] hi/lo ----
    for (int i = tid; i < 2048; i += 256) {
        int c = i >> 5, n4 = i & 31;
        float4 xv = *(const float4*)(x + (size_t)b * (CCH * NPIX) +
                                     (size_t)c * NPIX + n0 + n4 * 4);
        __half h0 = __float2half(xv.x), h1 = __float2half(xv.y);
        __half h2 = __float2half(xv.z), h3 = __float2half(xv.w);
        uint2 hi, lo;
        hi.x = h2u(h0, h1); hi.y = h2u(h2, h3);
        lo.x = pack_h2(xv.x - __half2float(h0), xv.y - __half2float(h1));
        lo.y = pack_h2(xv.z - __half2float(h2), xv.w - __half2float(h3));
        *(uint2*)(sm + SX_H + c * 272 + n4 * 8) = hi;
        *(uint2*)(sm + SX_L + c * 272 + n4 * 8) = lo;
    }
    float* sBias = (float*)(sm + SBIAS);
    float* sW2 = (float*)(sm + SW2B);
    float* sMval = (float*)(sm + SMVAL);
    float* sGSp = (float*)(sm + SGSP);
    for (int i = tid; i < 512; i += 256) {
        float v;
        if (i < 64)       v = bq[i];
        else if (i < 128) v = bk[i - 64];
        else if (i < 192) v = bv[i - 128];
        else if (i < 256) v = bg[i - 192];
        else              v = b1[i - 256];
        sBias[i] = v;
    }
    for (int i = tid; i < 256; i += 256) sW2[i] = W2[i];
    if (tid < 128) sMval[tid] = mask[b * NPIX + n0 + tid];
    __syncthreads();

    const uint32_t thrA = (uint32_t)(q8 + ((lane >> 3) & 1) * 8) * 144 +
                          ((lane >> 4) & 1) * 16;
    const uint32_t thrB = (uint32_t)(q8 + ((lane >> 3) & 1) * 8) * 272 +
                          ((lane >> 4) & 1) * 16;
    const float b2v = __ldg(b2);

    for (int nhalf = 0; nhalf < 2; nhalf++) {
        const int nb0 = nhalf * 64;
        for (int mpass = 0; mpass < 2; mpass++) {
            float d[2][8][4];
#pragma unroll
            for (int mt = 0; mt < 2; mt++)
#pragma unroll
                for (int nt = 0; nt < 8; nt++)
#pragma unroll
                    for (int q = 0; q < 4; q++) d[mt][nt][q] = 0.f;

            const uint32_t mrowbase = (uint32_t)(mpass * 256 + wid * 32) * 144;
#pragma unroll
            for (int pass = 0; pass < 3; pass++) {
                const uint32_t abase = sb + (pass < 2 ? SW_H : SW_L) + thrA + mrowbase;
                const uint32_t bbase = sb + (pass == 1 ? SX_L : SX_H) + thrB + nb0 * 2;
#pragma unroll
                for (int k = 0; k < 4; k++) {
                    uint32_t bf[4][4];
#pragma unroll
                    for (int ng = 0; ng < 4; ng++)
                        ldmx4t(bf[ng][0], bf[ng][1], bf[ng][2], bf[ng][3],
                               bbase + (uint32_t)k * (16 * 272) + ng * 32);
                    uint32_t af[2][4];
#pragma unroll
                    for (int mt = 0; mt < 2; mt++)
                        ldmx4(af[mt][0], af[mt][1], af[mt][2], af[mt][3],
                              abase + (uint32_t)mt * (16 * 144) + k * 32);
#pragma unroll
                    for (int mt = 0; mt < 2; mt++)
#pragma unroll
                        for (int ng = 0; ng < 4; ng++) {
                            mma_f16(d[mt][2 * ng], af[mt][0], af[mt][1], af[mt][2],
                                    af[mt][3], bf[ng][0], bf[ng][1]);
                            mma_f16(d[mt][2 * ng + 1], af[mt][0], af[mt][1], af[mt][2],
                                    af[mt][3], bf[ng][2], bf[ng][3]);
                        }
                }
            }

            if (mpass == 0) {
                const int sec = wid >> 1;
#pragma unroll
                for (int mt = 0; mt < 2; mt++) {
#pragma unroll
                    for (int ri = 0; ri < 2; ri++) {
                        const int ogl = wid * 32 + mt * 16 + g + ri * 8;
                        const int o = (wid & 1) * 32 + mt * 16 + g + ri * 8;
                        const float bias = sBias[ogl];
                        const size_t rowoff = (size_t)(b * 64 + o) * NPIX + n0;
#pragma unroll
                        for (int nt = 0; nt < 8; nt++) {
                            const int nl = nb0 + nt * 8 + 2 * t;
                            const float a0 = d[mt][nt][ri * 2 + 0];
                            const float a1 = d[mt][nt][ri * 2 + 1];
                            if (sec == 0 || sec == 1) {
                                const float m0 = sMval[nl], m1 = sMval[nl + 1];
                                const float v0 = bias + m0 * a0;
                                const float v1 = bias + m1 * a1;
                                if (sec == 0) {
                                    *(uint32_t*)(g_QhT + rowoff + nl) = pack_h2(v0, v1);
                                } else {
                                    *(uint32_t*)(g_KhT + rowoff + nl) = pack_h2(v0, v1);
                                }
                            } else if (sec == 2) {
                                const float v0 = bias + a0, v1 = bias + a1;
                                *(uint32_t*)(g_Vh + rowoff + nl) = pack_h2(v0, v1);
                            } else {
                                const float v0 = bias + a0, v1 = bias + a1;
                                float2 gg;
                                gg.x = 1.f / (1.f + __expf(-v0));
                                gg.y = 1.f / (1.f + __expf(-v1));
                                *(float2*)(g_G + rowoff + nl) = gg;
                            }
                        }
                    }
                }
            } else {
                float gsp[16];
#pragma unroll
                for (int i = 0; i < 16; i++) gsp[i] = 0.f;
#pragma unroll
                for (int mt = 0; mt < 2; mt++) {
#pragma unroll
                    for (int ri = 0; ri < 2; ri++) {
                        const int o = wid * 32 + mt * 16 + g + ri * 8;
                        const float bias = sBias[256 + o];
                        const float w2v = sW2[o];
#pragma unroll
                        for (int nt = 0; nt < 8; nt++) {
                            float h0 = bias + d[mt][nt][ri * 2 + 0];
                            float h1 = bias + d[mt][nt][ri * 2 + 1];
                            gsp[nt * 2 + 0] += w2v * fmaxf(h0, 0.f);
                            gsp[nt * 2 + 1] += w2v * fmaxf(h1, 0.f);
                        }
                    }
                }
#pragma unroll
                for (int off = 4; off < 32; off <<= 1)
#pragma unroll
                    for (int i = 0; i < 16; i++)
                        gsp[i] += __shfl_xor_sync(0xffffffffu, gsp[i], off);
                if (lane < 4) {
#pragma unroll
                    for (int nt = 0; nt < 8; nt++) {
                        sGSp[wid * 64 + nt * 8 + 2 * lane + 0] = gsp[nt * 2 + 0];
                        sGSp[wid * 64 + nt * 8 + 2 * lane + 1] = gsp[nt * 2 + 1];
                    }
                }
                __syncthreads();
                if (tid < 64) {
                    float s = b2v;
#pragma unroll
                    for (int w = 0; w < 8; w++) s += sGSp[w * 64 + tid];
                    g_GS[b * NPIX + n0 + nb0 + tid] = 1.f / (1.f + __expf(-s));
                }
                __syncthreads();
            }
        }
    }
}

// ---------------- fp16 flash attention: BM=128, f16x2 exp, ones-col lsum ----
#define KOFF 0
#define VOFF 17408
#define ABUFSZ 34816
#define QH_OFF (3 * ABUFSZ)            // 104448
#define SMEM_ATTN (QH_OFF + 17408)     // 121856
#define LOG2E 1.4426950408889634f
#define NSHIFT (-11.541560327111707f)  // -8 * log2(e)

__global__ __launch_bounds__(256, 1) void attn_kernel(
    const float* __restrict__ x, const unsigned int* __restrict__ flags,
    float* __restrict__ out) {
    const int b = blockIdx.y;
    const int m0 = blockIdx.x * 128;
    const int tid = threadIdx.x;

    if (flags[b] == 0u) {
        const float* xb = x + (size_t)b * (CCH * NPIX) + m0;
        float* ob = out + (size_t)b * (CCH * NPIX) + m0;
        for (int i = tid; i < 8192; i += 256) {
            int d = i >> 7, m = i & 127;
            ob[(size_t)d * NPIX + m] = xb[(size_t)d * NPIX + m];
        }
        return;
    }

    extern __shared__ __align__(16) char smem[];
    uint32_t sbase;
    asm("{ .reg .u64 t; cvta.to.shared.u64 t, %1; cvt.u32.u64 %0, t; }"
        : "=r"(sbase) : "l"(smem));

    const int wid = tid >> 5, lane = tid & 31;
    const int g = lane >> 2, t = lane & 3, q8 = lane & 7;
    const int rowA = wid * 16 + g;

    //   plain-A / trans-B : rows by bit3, col-half by bit4
    const uint32_t rA = q8 + ((lane >> 3) & 1) * 8;
    const uint32_t cA = ((lane >> 4) & 1) * 16;
    //   plain-B / trans-A : rows by bit4, col-half by bit3
    const uint32_t rB = q8 + ((lane >> 4) & 1) * 8;
    const uint32_t cB = ((lane >> 3) & 1) * 16;

    // constant B fragment: ones in column n=0 only (lanes g==0 hold k-elements)
    const uint32_t ones_b = (g == 0) ? 0x3C003C00u : 0u;

    const char* qh_g = (const char*)(g_QhT + (size_t)b * CCH * NPIX) + m0 * 2;
    const char* kh_g = (const char*)(g_KhT + (size_t)b * CCH * NPIX);
    const char* vh_g = (const char*)(g_Vh + (size_t)b * CCH * NPIX);

    // ---- prologue: Q + tile0 as group g0; tile1 as group g1 ----
#pragma unroll
    for (int i = 0; i < 4; i++) {
        int idx = tid + i * 256;           // 0..1023
        int row = idx >> 4, c16 = idx & 15;
        cp16(sbase + QH_OFF + row * 272 + c16 * 16, qh_g + row * 8192 + c16 * 16);
        cp16(sbase + KOFF + row * 272 + c16 * 16, kh_g + row * 8192 + c16 * 16);
        cp16(sbase + VOFF + row * 272 + c16 * 16, vh_g + row * 8192 + c16 * 16);
    }
    asm volatile("cp.async.commit_group;" ::: "memory");
#pragma unroll
    for (int i = 0; i < 4; i++) {
        int idx = tid + i * 256;
        int row = idx >> 4, c16 = idx & 15;
        cp16(sbase + ABUFSZ + KOFF + row * 272 + c16 * 16,
             kh_g + row * 8192 + 256 + c16 * 16);
        cp16(sbase + ABUFSZ + VOFF + row * 272 + c16 * 16,
             vh_g + row * 8192 + 256 + c16 * 16);
    }
    asm volatile("cp.async.commit_group;" ::: "memory");
    asm volatile("cp.async.wait_group 1;" ::: "memory");
    __syncthreads();

    // ---- Q A-fragments via ldmatrix.trans (trans-A selectors) ----
    uint32_t qah[4][4];
#pragma unroll
    for (int s = 0; s < 4; s++) {
        uint32_t qa = sbase + QH_OFF + (s * 16 + rB) * 272 + wid * 32 + cB;
        ldmx4t(qah[s][0], qah[s][1], qah[s][2], qah[s][3], qa);
    }

    float oD[8][4], oSum[4];
#pragma unroll
    for (int j = 0; j < 8; j++)
#pragma unroll
        for (int qq = 0; qq < 4; qq++) oD[j][qq] = 0.f;
#pragma unroll
    for (int qq = 0; qq < 4; qq++) oSum[qq] = 0.f;

    for (int tt = 0; tt < 32; tt++) {
        if (tt < 31) { asm volatile("cp.async.wait_group 1;" ::: "memory"); }
        else         { asm volatile("cp.async.wait_group 0;" ::: "memory"); }
        __syncthreads();

        if (tt + 2 < 32) {
            uint32_t nxt = sbase + ((tt + 2) % 3) * ABUFSZ;
            int nb = (tt + 2) * 256;
#pragma unroll
            for (int i = 0; i < 4; i++) {
                int idx = tid + i * 256;
                int row = idx >> 4, c16 = idx & 15;
                cp16(nxt + KOFF + row * 272 + c16 * 16,
                     kh_g + row * 8192 + nb + c16 * 16);
                cp16(nxt + VOFF + row * 272 + c16 * 16,
                     vh_g + row * 8192 + nb + c16 * 16);
            }
            asm volatile("cp.async.commit_group;" ::: "memory");
        }

        const uint32_t cur = sbase + (tt % 3) * ABUFSZ;

        // ---- S = Q K^T (single-pass fp16), K B-frags via ldmatrix.trans ----
        float sD[16][4];
#pragma unroll
        for (int j = 0; j < 16; j++)
#pragma unroll
            for (int qq = 0; qq < 4; qq++) sD[j][qq] = 0.f;

#pragma unroll
        for (int s = 0; s < 4; s++) {
            const uint32_t kb = cur + KOFF + (s * 16 + rA) * 272 + cA;
#pragma unroll
            for (int J = 0; J < 8; J++) {
                uint32_t b0, b1, b2, b3;
                ldmx4t(b0, b1, b2, b3, kb + J * 32);
                mma_f16(sD[2 * J], qah[s][0], qah[s][1], qah[s][2], qah[s][3], b0, b1);
                mma_f16(sD[2 * J + 1], qah[s][0], qah[s][1], qah[s][2], qah[s][3], b2, b3);
            }
        }

        // ---- P = exp(S - 8) via ex2.approx.f16x2 (packed, half MUFU) ----
        uint32_t pa[8][4];
#pragma unroll
        for (int j = 0; j < 16; j++) {
            float e0 = fmaf(sD[j][0], LOG2E, NSHIFT);
            float e1 = fmaf(sD[j][1], LOG2E, NSHIFT);
            float e2 = fmaf(sD[j][2], LOG2E, NSHIFT);
            float e3 = fmaf(sD[j][3], LOG2E, NSHIFT);
            int c = j >> 1, hi = (j & 1) << 1;
            pa[c][hi + 0] = ex2_h2(pack_h2(e0, e1));
            pa[c][hi + 1] = ex2_h2(pack_h2(e2, e3));
        }

        // ---- O += P V ; row-sum via ones-column mma ----
        const uint32_t vb = cur + VOFF + rB * 272 + cB;
#pragma unroll
        for (int c = 0; c < 8; c++) {
#pragma unroll
            for (int J = 0; J < 4; J++) {
                uint32_t v0, v1, v2, v3;
                ldmx4(v0, v1, v2, v3, vb + J * (16 * 272) + c * 32);
                mma_f16(oD[2 * J], pa[c][0], pa[c][1], pa[c][2], pa[c][3], v0, v1);
                mma_f16(oD[2 * J + 1], pa[c][0], pa[c][1], pa[c][2], pa[c][3], v2, v3);
            }
            mma_f16(oSum, pa[c][0], pa[c][1], pa[c][2], pa[c][3], ones_b, ones_b);
        }
    }

    // ---- row sums: col 0 of oSum, held by t==0 lane of each quad ----
    const float l0 = __shfl_sync(0xffffffffu, oSum[0], lane & ~3);
    const float l1 = __shfl_sync(0xffffffffu, oSum[2], lane & ~3);
    const float inv0 = 1.f / l0, inv1 = 1.f / l1;

    // ---- normalize + transpose to [d][m] (buf0 region; tile31 in buf2) ----
    float* tr = (float*)smem;   // 64 x 129 floats = 33 KB
#pragma unroll
    for (int j = 0; j < 8; j++) {
        int c0 = 8 * j + 2 * t;
        tr[c0 * 129 + rowA] = oD[j][0] * inv0;
        tr[(c0 + 1) * 129 + rowA] = oD[j][1] * inv0;
        tr[c0 * 129 + rowA + 8] = oD[j][2] * inv1;
        tr[(c0 + 1) * 129 + rowA + 8] = oD[j][3] * inv1;
    }
    __syncthreads();

    const float* gb = g_G + (size_t)b * 64 * NPIX + m0;
    const float* sb2 = g_GS + b * NPIX + m0;
    float* ob = out + (size_t)b * (CCH * NPIX) + m0;
    for (int i = tid; i < 8192; i += 256) {
        int d = i >> 7, m = i & 127;
        ob[(size_t)d * NPIX + m] = tr[d * 129 + m] * gb[(size_t)d * NPIX + m] * sb2[m];
    }
}

extern "C" void kernel_launch(void* const* d_in, const int* in_sizes, int n_in,
                              void* d_out, int out_size) {
    const float* x    = (const float*)d_in[0];
    const float* mask = (const float*)d_in[1];
    const unsigned int* flags = (const unsigned int*)d_in[2];
    const float* Wq = (const float*)d_in[3];
    const float* bq = (const float*)d_in[4];
    const float* Wk = (const float*)d_in[5];
    const float* bk = (const float*)d_in[6];
    const float* Wv = (const float*)d_in[7];
    const float* bv = (const float*)d_in[8];
    const float* Wg = (const float*)d_in[9];
    const float* bg = (const float*)d_in[10];
    const float* W1 = (const float*)d_in[11];
    const float* b1 = (const float*)d_in[12];
    const float* W2 = (const float*)d_in[13];
    const float* b2 = (const float*)d_in[14];
    float* out = (float*)d_out;

    cudaFuncSetAttribute(attn_kernel, cudaFuncAttributeMaxDynamicSharedMemorySize, SMEM_ATTN);
    cudaFuncSetAttribute(proj_mma, cudaFuncAttributeMaxDynamicSharedMemorySize, PROJ_SMEM);

    proj_mma<<<dim3(32, 8), 256, PROJ_SMEM>>>(x, mask, flags,
                                              Wq, bq, Wk, bk, Wv, bv, Wg, bg,
                                              W1, b1, W2, b2);
    attn_kernel<<<dim3(32, 8), 256, SMEM_ATTN>>>(x, flags, out);
}